// round 14
// baseline (speedup 1.0000x reference)
#include <cuda_runtime.h>
#include <cstdint>

#define NTOK 4096
#define DHID 2048
#define IEXP 8192
#define NE   8
#define G1   64

// ---------------- scratch ----------------
__device__ float g_T[NTOK * G1];
__device__ float g_coef[NTOK * 4];
__device__ float g_Smax[3];                       // 0: X, 1: Wg, 2: Wu
__device__ int8_t g_X1[(size_t)NTOK * DHID];      // X hi plane
__device__ int8_t g_X2[(size_t)NTOK * DHID];      // X lo plane
__device__ int8_t g_Wg1[(size_t)IEXP * DHID];     // Wg^T planes [I][D]
__device__ int8_t g_Wg2[(size_t)IEXP * DHID];
__device__ int8_t g_Wu1[(size_t)IEXP * DHID];
__device__ int8_t g_Wu2[(size_t)IEXP * DHID];
__device__ float g_Wd32[(size_t)IEXP * DHID];     // Wd tf32-rounded
__device__ float g_H[(size_t)NTOK * IEXP];        // swiglu out (tf32-rounded fp32)

// ---------------- helpers ----------------
__device__ __forceinline__ unsigned f2tf32(float x) {
    unsigned y; asm("cvt.rna.tf32.f32 %0, %1;" : "=r"(y) : "f"(x)); return y;
}
__device__ __forceinline__ float siluf(float z) { return z / (1.0f + __expf(-z)); }
__device__ __forceinline__ uint32_t smem_u32(const void* p) {
    uint32_t a;
    asm("{ .reg .u64 t; cvta.to.shared.u64 t, %1; cvt.u32.u64 %0, t; }" : "=r"(a) : "l"(p));
    return a;
}
__device__ __forceinline__ void cpa16(uint32_t d, const void* s) {
    asm volatile("cp.async.cg.shared.global [%0], [%1], 16;" :: "r"(d), "l"(s));
}
#define CPA_COMMIT() asm volatile("cp.async.commit_group;" ::: "memory")
#define CPA_WAIT(n)  asm volatile("cp.async.wait_group %0;" :: "n"(n) : "memory")

#define MMA_TF32(c, a, b)                                                        \
    asm volatile(                                                                \
        "mma.sync.aligned.m16n8k8.row.col.f32.tf32.tf32.f32 "                    \
        "{%0,%1,%2,%3}, {%4,%5,%6,%7}, {%8,%9}, {%0,%1,%2,%3};"                  \
        : "+f"((c)[0]), "+f"((c)[1]), "+f"((c)[2]), "+f"((c)[3])                 \
        : "r"((a)[0]), "r"((a)[1]), "r"((a)[2]), "r"((a)[3]),                    \
          "r"((b)[0]), "r"((b)[1]))

#define MMA_S8(c, a, b)                                                          \
    asm volatile(                                                                \
        "mma.sync.aligned.m16n8k32.row.col.s32.s8.s8.s32 "                       \
        "{%0,%1,%2,%3}, {%4,%5,%6,%7}, {%8,%9}, {%0,%1,%2,%3};"                  \
        : "+r"((c)[0]), "+r"((c)[1]), "+r"((c)[2]), "+r"((c)[3])                 \
        : "r"((a)[0]), "r"((a)[1]), "r"((a)[2]), "r"((a)[3]),                    \
          "r"((b)[0]), "r"((b)[1]))

// 15-bit fixed-point split: q = h*128 + l, h,l in s8
__device__ __forceinline__ void q15(float v, float invd, int8_t& h, int8_t& l) {
    int q = __float2int_rn(v * invd);
    q = max(-16319, min(16319, q));
    int hi = (q + 64) >> 7;
    h = (int8_t)hi; l = (int8_t)(q - (hi << 7));
}

// int8 gateup smem: per stage, A 128 rows x 44 words, B 64 rows x 44 words
// row layout per k32 chunk j (words j*20..j*20+19): hi bytes [0..7], lo [8..15], pad
#define GU_STG_W 8448
#define GU_SMEM  (2 * GU_STG_W * 4)    // 67584 -> 2 CTAs/SM

// down (tf32) smem: per stage A 128x36=4608, B 32x136=4352 -> 8960 words
#define DN_OFF_A(s) ((s) * 8960)
#define DN_OFF_B(s) ((s) * 8960 + 4608)
#define DN_SMEM (2 * 8960 * 4)         // 71680 -> 3 CTAs/SM

// ======================================================================
// Prep kernels
// ======================================================================
__global__ void init_scales_k() {
    if (threadIdx.x < 3) g_Smax[threadIdx.x] = 0.f;
}

__global__ __launch_bounds__(256) void absmax_all_k(
    const float* __restrict__ X, const float* __restrict__ Wg, const float* __restrict__ Wu)
{
    const int b = blockIdx.x, tid = threadIdx.x;
    const float4* src; size_t n4; float* out; int nb, b0;
    if (b < 1024)      { src = (const float4*)X;  n4 = (size_t)NTOK * DHID / 4; out = &g_Smax[0]; nb = 1024; b0 = b; }
    else if (b < 3072) { src = (const float4*)Wg; n4 = (size_t)DHID * IEXP / 4; out = &g_Smax[1]; nb = 2048; b0 = b - 1024; }
    else               { src = (const float4*)Wu; n4 = (size_t)DHID * IEXP / 4; out = &g_Smax[2]; nb = 2048; b0 = b - 3072; }
    float m = 0.f;
    for (size_t i = (size_t)b0 * 256 + tid; i < n4; i += (size_t)nb * 256) {
        float4 v = src[i];
        m = fmaxf(m, fmaxf(fmaxf(fabsf(v.x), fabsf(v.y)), fmaxf(fabsf(v.z), fabsf(v.w))));
    }
    #pragma unroll
    for (int s = 16; s > 0; s >>= 1)
        m = fmaxf(m, __shfl_xor_sync(0xffffffff, m, s));
    if ((tid & 31) == 0) atomicMax((int*)out, __float_as_int(m));
}

__global__ __launch_bounds__(256) void quant_x_k(const float* __restrict__ X)
{
    const float invd = 16384.f / g_Smax[0];
    int n4 = NTOK * DHID / 4;
    int stride = gridDim.x * blockDim.x;
    for (int i = blockIdx.x * blockDim.x + threadIdx.x; i < n4; i += stride) {
        float4 v = ((const float4*)X)[i];
        char4 h, l;
        q15(v.x, invd, (int8_t&)h.x, (int8_t&)l.x);
        q15(v.y, invd, (int8_t&)h.y, (int8_t&)l.y);
        q15(v.z, invd, (int8_t&)h.z, (int8_t&)l.z);
        q15(v.w, invd, (int8_t&)h.w, (int8_t&)l.w);
        ((char4*)g_X1)[i] = h;
        ((char4*)g_X2)[i] = l;
    }
}

// W [R=DHID][C=IEXP] fp32 -> planes [C][R] s8
__global__ __launch_bounds__(256) void quant_wT_k(
    const float* __restrict__ W, int8_t* __restrict__ p1, int8_t* __restrict__ p2, int si)
{
    __shared__ float t[32][33];
    const float invd = 16384.f / g_Smax[si];
    int c0 = blockIdx.x * 32, r0 = blockIdx.y * 32;
    int tx = threadIdx.x, ty = threadIdx.y;
    #pragma unroll
    for (int j = 0; j < 32; j += 8)
        t[ty + j][tx] = W[(size_t)(r0 + ty + j) * IEXP + c0 + tx];
    __syncthreads();
    #pragma unroll
    for (int j = 0; j < 32; j += 8) {
        int8_t h, l;
        q15(t[tx][ty + j], invd, h, l);
        size_t o = (size_t)(c0 + ty + j) * DHID + r0 + tx;
        p1[o] = h; p2[o] = l;
    }
}

__global__ __launch_bounds__(256) void round_tf32_k(
    const float* __restrict__ src, float* __restrict__ dst, int n4)
{
    int i = blockIdx.x * blockDim.x + threadIdx.x;
    int stride = gridDim.x * blockDim.x;
    for (; i < n4; i += stride) {
        float4 v = ((const float4*)src)[i];
        v.x = __uint_as_float(f2tf32(v.x)); v.y = __uint_as_float(f2tf32(v.y));
        v.z = __uint_as_float(f2tf32(v.z)); v.w = __uint_as_float(f2tf32(v.w));
        ((float4*)dst)[i] = v;
    }
}

// ======================================================================
// Router stage A: T = tanh(X @ gate_w1)
// ======================================================================
__global__ __launch_bounds__(256) void router_gemm_tanh(
    const float* __restrict__ X, const float* __restrict__ W1)
{
    __shared__ float Xs[32][65];
    __shared__ float Ws[32][64];
    const int tid = threadIdx.x;
    const int tx = tid & 15, ty = tid >> 4;
    const int m0 = blockIdx.x * 64;

    float acc[4][4] = {};
    for (int k0 = 0; k0 < DHID; k0 += 32) {
        __syncthreads();
        #pragma unroll
        for (int i = 0; i < 8; i++) {
            int e = tid + i * 256;
            Xs[e & 31][e >> 5] = X[(size_t)(m0 + (e >> 5)) * DHID + k0 + (e & 31)];
        }
        #pragma unroll
        for (int i = 0; i < 8; i++) {
            int e = tid + i * 256;
            Ws[e >> 6][e & 63] = W1[(size_t)(k0 + (e >> 6)) * G1 + (e & 63)];
        }
        __syncthreads();
        #pragma unroll
        for (int k = 0; k < 32; k++) {
            float av[4], bv[4];
            #pragma unroll
            for (int i = 0; i < 4; i++) av[i] = Xs[k][ty * 4 + i];
            #pragma unroll
            for (int j = 0; j < 4; j++) bv[j] = Ws[k][tx * 4 + j];
            #pragma unroll
            for (int i = 0; i < 4; i++)
                #pragma unroll
                for (int j = 0; j < 4; j++)
                    acc[i][j] = fmaf(av[i], bv[j], acc[i][j]);
        }
    }
    #pragma unroll
    for (int i = 0; i < 4; i++)
        #pragma unroll
        for (int j = 0; j < 4; j++)
            g_T[(size_t)(m0 + ty * 4 + i) * G1 + tx * 4 + j] = tanhf(acc[i][j]);
}

// ======================================================================
// Router stage B
// ======================================================================
__global__ __launch_bounds__(128) void router_combine(
    const float* __restrict__ X, const float* __restrict__ W2,
    const float* __restrict__ ceWg, float* __restrict__ logits_out)
{
    const int n = blockIdx.x;
    const int tid = threadIdx.x;
    __shared__ float red[4][128];
    __shared__ float lg[8];

    float pg0 = 0.f, pg1 = 0.f, pg2 = 0.f, pg3 = 0.f;
    for (int k = tid; k < DHID; k += 128) {
        float xv = X[(size_t)n * DHID + k];
        pg0 = fmaf(xv, ceWg[k * 2 + 0], pg0);
        pg1 = fmaf(xv, ceWg[k * 2 + 1], pg1);
        pg2 = fmaf(xv, ceWg[DHID * 2 + k * 2 + 0], pg2);
        pg3 = fmaf(xv, ceWg[DHID * 2 + k * 2 + 1], pg3);
    }
    red[0][tid] = pg0; red[1][tid] = pg1; red[2][tid] = pg2; red[3][tid] = pg3;
    __syncthreads();
    for (int s = 64; s > 0; s >>= 1) {
        if (tid < s) {
            #pragma unroll
            for (int j = 0; j < 4; j++) red[j][tid] += red[j][tid + s];
        }
        __syncthreads();
    }
    if (tid < NE) {
        float s = 0.f;
        #pragma unroll 8
        for (int i = 0; i < G1; i++)
            s = fmaf(g_T[(size_t)n * G1 + i], W2[i * NE + tid], s);
        lg[tid] = s;
        logits_out[(size_t)n * NE + tid] = s;
    }
    __syncthreads();
    if (tid == 0) {
        float p[NE];
        float mx = lg[0];
        #pragma unroll
        for (int e = 1; e < NE; e++) mx = fmaxf(mx, lg[e]);
        float sum = 0.f;
        #pragma unroll
        for (int e = 0; e < NE; e++) { p[e] = __expf(lg[e] - mx); sum += p[e]; }
        float inv = 1.f / sum;
        #pragma unroll
        for (int e = 0; e < NE; e++) p[e] *= inv;
        int i0 = 0;
        #pragma unroll
        for (int e = 1; e < NE; e++) if (p[e] > p[i0]) i0 = e;
        int i1 = (i0 == 0) ? 1 : 0;
        #pragma unroll
        for (int e = 0; e < NE; e++) if (e != i0 && p[e] > p[i1]) i1 = e;
        float w0 = (i0 == NE - 1) ? 0.f : p[i0];
        float w1 = (i1 == NE - 1) ? 0.f : p[i1];
        float winv = 1.f / (w0 + w1);
        w0 *= winv; w1 *= winv;
        float pe[NE];
        #pragma unroll
        for (int e = 0; e < NE; e++) pe[e] = 0.f;
        pe[i0] += w0; pe[i1] += w1;
        float cw0x = 1.f / (1.f + __expf(red[1][0] - red[0][0]));
        float cw1x = 1.f / (1.f + __expf(red[3][0] - red[2][0]));
        g_coef[n * 4 + 0] = pe[0] + pe[2] * cw0x + pe[3] * cw1x;
        g_coef[n * 4 + 1] = pe[2] * (1.f - cw0x);
        g_coef[n * 4 + 2] = pe[3] * (1.f - cw1x);
        g_coef[n * 4 + 3] = pe[4] + pe[5] + pe[6] + pe[7];
    }
}

// ======================================================================
// GEMM 1 (int8 x3 split): H = silu(X@Wg) * (X@Wu)
// CTA: 256 thr (8 warps, 4m x 2n), tile M=128 x mmaN=64 (G32|U32).
// Warp tile m32 x n32. k-tile 64 (2 x k32 chunks), 2-stage cp.async, 2 CTAs/SM.
// acc1 = sum a1*b1 (weight 2^14), acc2 = sum a1*b2 + a2*b1 (weight 2^7).
// ======================================================================
__global__ __launch_bounds__(256, 2) void gemm_gateup_i8()
{
    extern __shared__ unsigned sm[];
    const uint32_t sa = smem_u32(sm);
    const int tid = threadIdx.x;
    const int lane = tid & 31, wid = tid >> 5;
    const int wm = wid & 3, wn = wid >> 2;      // 4 x 2
    const int g = lane >> 2, tg = lane & 3;
    const int m0 = blockIdx.x * 128;
    const int n0 = blockIdx.y * 32;             // H columns per CTA
    const int KT = DHID / 64;                   // 32

    int acc1[2][4][4] = {};
    int acc2[2][4][4] = {};

    auto issue = [&](int kt) {
        int s = kt & 1, k0 = kt * 64;
        uint32_t base = sa + (s * GU_STG_W) * 4;
        #pragma unroll
        for (int i = 0; i < 4; i++) {            // A: 128 rows x 8 chunks
            int e = tid + i * 256;
            int r = e >> 3, sub = e & 7;
            int j = sub >> 2, p = (sub >> 1) & 1, h = sub & 1;
            const int8_t* src = (p ? g_X2 : g_X1) + (size_t)(m0 + r) * DHID + k0 + j * 32 + h * 16;
            cpa16(base + (r * 44 + j * 20 + p * 8 + h * 4) * 4, src);
        }
        #pragma unroll
        for (int i = 0; i < 2; i++) {            // B: 64 n-rows x 8 chunks
            int e = tid + i * 256;
            int n = e >> 3, sub = e & 7;
            int j = sub >> 2, p = (sub >> 1) & 1, h = sub & 1;
            const int8_t* src;
            if (n < 32) src = (p ? g_Wg2 : g_Wg1) + (size_t)(n0 + n) * DHID + k0 + j * 32 + h * 16;
            else        src = (p ? g_Wu2 : g_Wu1) + (size_t)(n0 + n - 32) * DHID + k0 + j * 32 + h * 16;
            cpa16(base + (5632 + n * 44 + j * 20 + p * 8 + h * 4) * 4, src);
        }
        CPA_COMMIT();
    };

    issue(0);
    const int arow = wm * 32;
    const int bcol = wn * 32;

    for (int kt = 0; kt < KT; kt++) {
        CPA_WAIT(0);
        __syncthreads();
        if (kt + 1 < KT) issue(kt + 1);
        const unsigned* As = sm + (kt & 1) * GU_STG_W;
        const unsigned* Bs = As + 5632;
        #pragma unroll
        for (int j = 0; j < 2; j++) {
            const int cb = j * 20;
            unsigned ah[2][4], bh[4][2];
            #pragma unroll
            for (int mi = 0; mi < 2; mi++) {
                int rb = (arow + mi * 16 + g) * 44 + cb;
                ah[mi][0] = As[rb + tg];
                ah[mi][1] = As[rb + 352 + tg];        // +8 rows
                ah[mi][2] = As[rb + 4 + tg];
                ah[mi][3] = As[rb + 352 + 4 + tg];
            }
            #pragma unroll
            for (int ni = 0; ni < 4; ni++) {
                int nb = (bcol + ni * 8 + g) * 44 + cb;
                bh[ni][0] = Bs[nb + tg];
                bh[ni][1] = Bs[nb + 4 + tg];
            }
            #pragma unroll
            for (int mi = 0; mi < 2; mi++)
                #pragma unroll
                for (int ni = 0; ni < 4; ni++)
                    MMA_S8(acc1[mi][ni], ah[mi], bh[ni]);
            unsigned bl[4][2];
            #pragma unroll
            for (int ni = 0; ni < 4; ni++) {
                int nb = (bcol + ni * 8 + g) * 44 + cb;
                bl[ni][0] = Bs[nb + 8 + tg];
                bl[ni][1] = Bs[nb + 12 + tg];
            }
            #pragma unroll
            for (int mi = 0; mi < 2; mi++)
                #pragma unroll
                for (int ni = 0; ni < 4; ni++)
                    MMA_S8(acc2[mi][ni], ah[mi], bl[ni]);
            unsigned al[2][4];
            #pragma unroll
            for (int mi = 0; mi < 2; mi++) {
                int rb = (arow + mi * 16 + g) * 44 + cb;
                al[mi][0] = As[rb + 8 + tg];
                al[mi][1] = As[rb + 352 + 8 + tg];
                al[mi][2] = As[rb + 12 + tg];
                al[mi][3] = As[rb + 352 + 12 + tg];
            }
            #pragma unroll
            for (int mi = 0; mi < 2; mi++)
                #pragma unroll
                for (int ni = 0; ni < 4; ni++)
                    MMA_S8(acc2[mi][ni], al[mi], bh[ni]);
        }
    }
    __syncthreads();

    // epilogue: dequant -> Hs [128][66] fp32, pair G/U, write g_H tf32-rounded
    float* Hs = (float*)sm;
    {
        const float kq = 1.f / 16384.f;
        float Sx = g_Smax[0];
        float sG = (Sx * kq) * (g_Smax[1] * kq);
        float sU = (Sx * kq) * (g_Smax[2] * kq);
        float sc = (wn == 0) ? sG : sU;
        #pragma unroll
        for (int mi = 0; mi < 2; mi++) {
            int r1 = arow + mi * 16 + g, r2 = r1 + 8;
            #pragma unroll
            for (int ni = 0; ni < 4; ni++) {
                int col = bcol + ni * 8 + 2 * tg;
                int* c1 = acc1[mi][ni];
                int* c2 = acc2[mi][ni];
                Hs[r1 * 66 + col]     = ((float)c1[0] * 16384.f + (float)c2[0] * 128.f) * sc;
                Hs[r1 * 66 + col + 1] = ((float)c1[1] * 16384.f + (float)c2[1] * 128.f) * sc;
                Hs[r2 * 66 + col]     = ((float)c1[2] * 16384.f + (float)c2[2] * 128.f) * sc;
                Hs[r2 * 66 + col + 1] = ((float)c1[3] * 16384.f + (float)c2[3] * 128.f) * sc;
            }
        }
    }
    __syncthreads();
    #pragma unroll
    for (int i = 0; i < 16; i++) {
        int e = tid + i * 256;
        int r = e >> 5, c = e & 31;
        float gv = Hs[r * 66 + c];
        float uv = Hs[r * 66 + 32 + c];
        g_H[(size_t)(m0 + r) * IEXP + n0 + c] = __uint_as_float(f2tf32(siluf(gv) * uv));
    }
}

// ======================================================================
// GEMM 2 (tf32, R10 champion): out = cs*(H@Wd) + cx*x + cc0*c0 + cc1*c1
// CTA: 128 thr (4 warps, 2x2), tile M=128 x N=128, warp m64xn64, 3 CTAs/SM.
// ======================================================================
__global__ __launch_bounds__(128, 3) void gemm_down(
    const float* __restrict__ X,
    const float* __restrict__ ceC,
    float* __restrict__ out)
{
    extern __shared__ unsigned sm[];
    const uint32_t sa = smem_u32(sm);
    const int tid = threadIdx.x;
    const int lane = tid & 31, wid = tid >> 5;
    const int wm = wid & 1, wn = wid >> 1;
    const int g = lane >> 2, tg = lane & 3;
    const int m0 = blockIdx.x * 128;
    const int n0 = blockIdx.y * 128;
    const int KT = IEXP / 32;

    float acc[4][8][4] = {};

    auto issue = [&](int kt) {
        int s = kt & 1, k0 = kt * 32;
        #pragma unroll
        for (int i = 0; i < 8; i++) {
            int e = tid + i * 128;
            int r = e >> 3, q = e & 7;
            cpa16(sa + (DN_OFF_A(s) + r * 36 + q * 4) * 4,
                  g_H + (size_t)(m0 + r) * IEXP + k0 + q * 4);
        }
        #pragma unroll
        for (int i = 0; i < 8; i++) {
            int e = tid + i * 128;
            int kk = e >> 5, c8 = e & 31;
            cpa16(sa + (DN_OFF_B(s) + kk * 136 + c8 * 4) * 4,
                  g_Wd32 + (size_t)(k0 + kk) * DHID + n0 + c8 * 4);
        }
        CPA_COMMIT();
    };

    issue(0);
    const int arow = wm * 64;
    const int bcol = wn * 64;

    for (int kt = 0; kt < KT; kt++) {
        CPA_WAIT(0);
        __syncthreads();
        if (kt + 1 < KT) issue(kt + 1);
        const unsigned* As = sm + DN_OFF_A(kt & 1);
        const unsigned* Bs = sm + DN_OFF_B(kt & 1);
        #pragma unroll
        for (int ks = 0; ks < 4; ks++) {
            int c = ks * 8 + tg;
            unsigned a[4][4];
            #pragma unroll
            for (int mi = 0; mi < 4; mi++) {
                int r = arow + mi * 16 + g;
                a[mi][0] = As[r * 36 + c];
                a[mi][1] = As[(r + 8) * 36 + c];
                a[mi][2] = As[r * 36 + c + 4];
                a[mi][3] = As[(r + 8) * 36 + c + 4];
            }
            unsigned b[8][2];
            #pragma unroll
            for (int ni = 0; ni < 8; ni++) {
                int nn = bcol + ni * 8 + g;
                b[ni][0] = Bs[c * 136 + nn];
                b[ni][1] = Bs[(c + 4) * 136 + nn];
            }
            #pragma unroll
            for (int mi = 0; mi < 4; mi++)
                #pragma unroll
                for (int ni = 0; ni < 8; ni++)
                    MMA_TF32(acc[mi][ni], a[mi], b[ni]);
        }
    }

    const float* c0 = ceC;
    const float* c1 = ceC + DHID;
    #pragma unroll
    for (int mi = 0; mi < 4; mi++) {
        int r1 = m0 + arow + mi * 16 + g;
        int r2 = r1 + 8;
        float cx1 = g_coef[r1 * 4 + 0], cc01 = g_coef[r1 * 4 + 1],
              cc11 = g_coef[r1 * 4 + 2], cs1 = g_coef[r1 * 4 + 3];
        float cx2 = g_coef[r2 * 4 + 0], cc02 = g_coef[r2 * 4 + 1],
              cc12 = g_coef[r2 * 4 + 2], cs2 = g_coef[r2 * 4 + 3];
        #pragma unroll
        for (int ni = 0; ni < 8; ni++) {
            int nn = n0 + bcol + ni * 8 + 2 * tg;
            float* c = acc[mi][ni];
            float2 x1 = *(const float2*)(X + (size_t)r1 * DHID + nn);
            float2 x2 = *(const float2*)(X + (size_t)r2 * DHID + nn);
            float2 v0 = *(const float2*)(c0 + nn);
            float2 v1 = *(const float2*)(c1 + nn);
            float2 o1, o2;
            o1.x = cs1 * c[0] + cx1 * x1.x + cc01 * v0.x + cc11 * v1.x;
            o1.y = cs1 * c[1] + cx1 * x1.y + cc01 * v0.y + cc11 * v1.y;
            o2.x = cs2 * c[2] + cx2 * x2.x + cc02 * v0.x + cc12 * v1.x;
            o2.y = cs2 * c[3] + cx2 * x2.y + cc02 * v0.y + cc12 * v1.y;
            *(float2*)(out + (size_t)r1 * DHID + nn) = o1;
            *(float2*)(out + (size_t)r2 * DHID + nn) = o2;
        }
    }
}

// ======================================================================
extern "C" void kernel_launch(void* const* d_in, const int* in_sizes, int n_in,
                              void* d_out, int out_size)
{
    const float* X    = (const float*)d_in[0];
    const float* W1   = (const float*)d_in[1];
    const float* W2   = (const float*)d_in[2];
    const float* ceWg = (const float*)d_in[3];
    const float* ceC  = (const float*)d_in[4];
    const float* Wg   = (const float*)d_in[5];
    const float* Wu   = (const float*)d_in[6];
    const float* Wd   = (const float*)d_in[7];
    float* out = (float*)d_out;
    float* logits = out + (size_t)NTOK * DHID;

    cudaFuncSetAttribute(gemm_gateup_i8, cudaFuncAttributeMaxDynamicSharedMemorySize, GU_SMEM);
    cudaFuncSetAttribute(gemm_down, cudaFuncAttributeMaxDynamicSharedMemorySize, DN_SMEM);

    int8_t *pWg1, *pWg2, *pWu1, *pWu2;
    float *pWd32;
    cudaGetSymbolAddress((void**)&pWg1, g_Wg1);
    cudaGetSymbolAddress((void**)&pWg2, g_Wg2);
    cudaGetSymbolAddress((void**)&pWu1, g_Wu1);
    cudaGetSymbolAddress((void**)&pWu2, g_Wu2);
    cudaGetSymbolAddress((void**)&pWd32, g_Wd32);

    // Launch order: gateup at index 5 for ncu -s 5 -c 1.
    init_scales_k<<<1, 32>>>();                                             // 0
    absmax_all_k<<<5120, 256>>>(X, Wg, Wu);                                 // 1
    quant_x_k<<<1024, 256>>>(X);                                            // 2
    quant_wT_k<<<dim3(IEXP / 32, DHID / 32), dim3(32, 8)>>>(Wg, pWg1, pWg2, 1);  // 3
    quant_wT_k<<<dim3(IEXP / 32, DHID / 32), dim3(32, 8)>>>(Wu, pWu1, pWu2, 2);  // 4
    gemm_gateup_i8<<<dim3(NTOK / 128, IEXP / 32), 256, GU_SMEM>>>();        // 5 <- profiled
    round_tf32_k<<<2048, 256>>>(Wd, pWd32, IEXP * DHID / 4);                // 6
    router_gemm_tanh<<<NTOK / 64, 256>>>(X, W1);                            // 7
    router_combine<<<NTOK, 128>>>(X, W2, ceWg, logits);                     // 8
    gemm_down<<<dim3(NTOK / 128, DHID / 128), 128, DN_SMEM>>>(X, ceC, out); // 9
}

// round 16
// speedup vs baseline: 3.0121x; 3.0121x over previous
#include <cuda_runtime.h>
#include <cstdint>

#define NTOK 4096
#define DHID 2048
#define IEXP 8192
#define NE   8
#define G1   64

// ---------------- scratch ----------------
__device__ float g_T[NTOK * G1];
__device__ float g_coef[NTOK * 4];
__device__ float g_X32[(size_t)NTOK * DHID];     // tf32-rounded, k-octet permuted
__device__ float g_Wg32[(size_t)DHID * IEXP];
__device__ float g_Wu32[(size_t)DHID * IEXP];
__device__ float g_Wd32[(size_t)IEXP * DHID];
__device__ float g_H[(size_t)NTOK * IEXP];       // tf32-rounded, k-octet permuted

// ---------------- helpers ----------------
__device__ __forceinline__ unsigned f2tf32(float x) {
    unsigned y; asm("cvt.rna.tf32.f32 %0, %1;" : "=r"(y) : "f"(x)); return y;
}
__device__ __forceinline__ float siluf(float z) { return z / (1.0f + __expf(-z)); }
__device__ __forceinline__ uint32_t smem_u32(const void* p) {
    uint32_t a;
    asm("{ .reg .u64 t; cvta.to.shared.u64 t, %1; cvt.u32.u64 %0, t; }" : "=r"(a) : "l"(p));
    return a;
}
__device__ __forceinline__ void cpa16(uint32_t d, const void* s) {
    asm volatile("cp.async.cg.shared.global [%0], [%1], 16;" :: "r"(d), "l"(s));
}
#define CPA_COMMIT() asm volatile("cp.async.commit_group;" ::: "memory")
#define CPA_WAIT(n)  asm volatile("cp.async.wait_group %0;" :: "n"(n) : "memory")

#define MMA_TF32(c, a, b)                                                        \
    asm volatile(                                                                \
        "mma.sync.aligned.m16n8k8.row.col.f32.tf32.tf32.f32 "                    \
        "{%0,%1,%2,%3}, {%4,%5,%6,%7}, {%8,%9}, {%0,%1,%2,%3};"                  \
        : "+f"((c)[0]), "+f"((c)[1]), "+f"((c)[2]), "+f"((c)[3])                 \
        : "r"((a)[0]), "r"((a)[1]), "r"((a)[2]), "r"((a)[3]),                    \
          "r"((b)[0]), "r"((b)[1]))

// octet permutation: physical j holds original c with p(c)=j
// p(c) = (c&~7) | ((c&3)<<1) | ((c>>2)&1)  -> pairs (tg, tg+4) adjacent
__device__ __host__ __forceinline__ int p8(int c) {
    return (c & ~7) | ((c & 3) << 1) | ((c >> 2) & 1);
}

// per stage (words): A 128x40 = 5120 (stride 40 -> LDS.64 conflict-free),
// B 32x136 = 4352 -> 9472 words/stage
#define OFF_A(s) ((s) * 9472)
#define OFF_B(s) ((s) * 9472 + 5120)
#define SMEM_BYTES (2 * 9472 * 4)   // 75776 B, 2 stages -> 3 CTAs/SM (227.3KB/228KB)

// ======================================================================
// Prep: tf32 round (weights, elementwise)
// ======================================================================
__global__ __launch_bounds__(256) void round_tf32_k(
    const float* __restrict__ src, float* __restrict__ dst, int n4)
{
    int i = blockIdx.x * blockDim.x + threadIdx.x;
    int stride = gridDim.x * blockDim.x;
    for (; i < n4; i += stride) {
        float4 v = ((const float4*)src)[i];
        v.x = __uint_as_float(f2tf32(v.x)); v.y = __uint_as_float(f2tf32(v.y));
        v.z = __uint_as_float(f2tf32(v.z)); v.w = __uint_as_float(f2tf32(v.w));
        ((float4*)dst)[i] = v;
    }
}

// Prep for X: tf32 round + k-octet permute.
// out octet: [lo.x, hi.x, lo.y, hi.y, lo.z, hi.z, lo.w, hi.w]
__global__ __launch_bounds__(256) void round_perm_k(
    const float* __restrict__ src, float* __restrict__ dst, int n8)
{
    int i = blockIdx.x * blockDim.x + threadIdx.x;
    int stride = gridDim.x * blockDim.x;
    for (; i < n8; i += stride) {
        float4 lo = ((const float4*)src)[i * 2];
        float4 hi = ((const float4*)src)[i * 2 + 1];
        float4 o1, o2;
        o1.x = __uint_as_float(f2tf32(lo.x)); o1.y = __uint_as_float(f2tf32(hi.x));
        o1.z = __uint_as_float(f2tf32(lo.y)); o1.w = __uint_as_float(f2tf32(hi.y));
        o2.x = __uint_as_float(f2tf32(lo.z)); o2.y = __uint_as_float(f2tf32(hi.z));
        o2.z = __uint_as_float(f2tf32(lo.w)); o2.w = __uint_as_float(f2tf32(hi.w));
        ((float4*)dst)[i * 2] = o1;
        ((float4*)dst)[i * 2 + 1] = o2;
    }
}

// ======================================================================
// Router stage A: T = tanh(X @ gate_w1)
// ======================================================================
__global__ __launch_bounds__(256) void router_gemm_tanh(
    const float* __restrict__ X, const float* __restrict__ W1)
{
    __shared__ float Xs[32][65];
    __shared__ float Ws[32][64];
    const int tid = threadIdx.x;
    const int tx = tid & 15, ty = tid >> 4;
    const int m0 = blockIdx.x * 64;

    float acc[4][4] = {};
    for (int k0 = 0; k0 < DHID; k0 += 32) {
        __syncthreads();
        #pragma unroll
        for (int i = 0; i < 8; i++) {
            int e = tid + i * 256;
            Xs[e & 31][e >> 5] = X[(size_t)(m0 + (e >> 5)) * DHID + k0 + (e & 31)];
        }
        #pragma unroll
        for (int i = 0; i < 8; i++) {
            int e = tid + i * 256;
            Ws[e >> 6][e & 63] = W1[(size_t)(k0 + (e >> 6)) * G1 + (e & 63)];
        }
        __syncthreads();
        #pragma unroll
        for (int k = 0; k < 32; k++) {
            float av[4], bv[4];
            #pragma unroll
            for (int i = 0; i < 4; i++) av[i] = Xs[k][ty * 4 + i];
            #pragma unroll
            for (int j = 0; j < 4; j++) bv[j] = Ws[k][tx * 4 + j];
            #pragma unroll
            for (int i = 0; i < 4; i++)
                #pragma unroll
                for (int j = 0; j < 4; j++)
                    acc[i][j] = fmaf(av[i], bv[j], acc[i][j]);
        }
    }
    #pragma unroll
    for (int i = 0; i < 4; i++)
        #pragma unroll
        for (int j = 0; j < 4; j++)
            g_T[(size_t)(m0 + ty * 4 + i) * G1 + tx * 4 + j] = tanhf(acc[i][j]);
}

// ======================================================================
// Router stage B
// ======================================================================
__global__ __launch_bounds__(128) void router_combine(
    const float* __restrict__ X, const float* __restrict__ W2,
    const float* __restrict__ ceWg, float* __restrict__ logits_out)
{
    const int n = blockIdx.x;
    const int tid = threadIdx.x;
    __shared__ float red[4][128];
    __shared__ float lg[8];

    float pg0 = 0.f, pg1 = 0.f, pg2 = 0.f, pg3 = 0.f;
    for (int k = tid; k < DHID; k += 128) {
        float xv = X[(size_t)n * DHID + k];
        pg0 = fmaf(xv, ceWg[k * 2 + 0], pg0);
        pg1 = fmaf(xv, ceWg[k * 2 + 1], pg1);
        pg2 = fmaf(xv, ceWg[DHID * 2 + k * 2 + 0], pg2);
        pg3 = fmaf(xv, ceWg[DHID * 2 + k * 2 + 1], pg3);
    }
    red[0][tid] = pg0; red[1][tid] = pg1; red[2][tid] = pg2; red[3][tid] = pg3;
    __syncthreads();
    for (int s = 64; s > 0; s >>= 1) {
        if (tid < s) {
            #pragma unroll
            for (int j = 0; j < 4; j++) red[j][tid] += red[j][tid + s];
        }
        __syncthreads();
    }
    if (tid < NE) {
        float s = 0.f;
        #pragma unroll 8
        for (int i = 0; i < G1; i++)
            s = fmaf(g_T[(size_t)n * G1 + i], W2[i * NE + tid], s);
        lg[tid] = s;
        logits_out[(size_t)n * NE + tid] = s;
    }
    __syncthreads();
    if (tid == 0) {
        float p[NE];
        float mx = lg[0];
        #pragma unroll
        for (int e = 1; e < NE; e++) mx = fmaxf(mx, lg[e]);
        float sum = 0.f;
        #pragma unroll
        for (int e = 0; e < NE; e++) { p[e] = __expf(lg[e] - mx); sum += p[e]; }
        float inv = 1.f / sum;
        #pragma unroll
        for (int e = 0; e < NE; e++) p[e] *= inv;
        int i0 = 0;
        #pragma unroll
        for (int e = 1; e < NE; e++) if (p[e] > p[i0]) i0 = e;
        int i1 = (i0 == 0) ? 1 : 0;
        #pragma unroll
        for (int e = 0; e < NE; e++) if (e != i0 && p[e] > p[i1]) i1 = e;
        float w0 = (i0 == NE - 1) ? 0.f : p[i0];
        float w1 = (i1 == NE - 1) ? 0.f : p[i1];
        float winv = 1.f / (w0 + w1);
        w0 *= winv; w1 *= winv;
        float pe[NE];
        #pragma unroll
        for (int e = 0; e < NE; e++) pe[e] = 0.f;
        pe[i0] += w0; pe[i1] += w1;
        float cw0x = 1.f / (1.f + __expf(red[1][0] - red[0][0]));
        float cw1x = 1.f / (1.f + __expf(red[3][0] - red[2][0]));
        g_coef[n * 4 + 0] = pe[0] + pe[2] * cw0x + pe[3] * cw1x;
        g_coef[n * 4 + 1] = pe[2] * (1.f - cw0x);
        g_coef[n * 4 + 2] = pe[3] * (1.f - cw1x);
        g_coef[n * 4 + 3] = pe[4] + pe[5] + pe[6] + pe[7];
    }
}

// ======================================================================
// GEMM 1: H = silu(X@Wg) * (X@Wu)
// CTA: 128 threads (4 warps, 2x2), tile M=128 x mmaN=128 (G|U 64 each).
// Warp tile m64 x n64, 2-stage cp.async, 3 CTAs/SM.
// A is k-octet-permuted: fragment pair (tg, tg+4) = one LDS.64.
// ======================================================================
__global__ __launch_bounds__(128, 3) void gemm_gateup()
{
    extern __shared__ unsigned sm[];
    const uint32_t sa = smem_u32(sm);
    const int tid = threadIdx.x;
    const int lane = tid & 31, wid = tid >> 5;
    const int wm = wid & 1, wn = wid >> 1;          // 2x2
    const int g = lane >> 2, tg = lane & 3;
    const int m0 = blockIdx.x * 128;
    const int n0 = blockIdx.y * 64;
    const int KT = DHID / 32;

    float acc[4][8][4] = {};

    auto issue = [&](int kt) {
        int s = kt & 1, k0 = kt * 32;
        #pragma unroll
        for (int i = 0; i < 8; i++) {                 // A: permuted X, contiguous
            int e = tid + i * 128;
            int r = e >> 3, q = e & 7;
            cpa16(sa + (OFF_A(s) + r * 40 + q * 4) * 4,
                  g_X32 + (size_t)(m0 + r) * DHID + k0 + q * 4);
        }
        #pragma unroll
        for (int i = 0; i < 8; i++) {                 // B: 32 k-rows x 128 cols
            int e = tid + i * 128;
            int kk = e >> 5, c8 = e & 31;
            const float* src = (c8 < 16)
                ? g_Wg32 + (size_t)(k0 + kk) * IEXP + n0 + c8 * 4
                : g_Wu32 + (size_t)(k0 + kk) * IEXP + n0 + (c8 - 16) * 4;
            cpa16(sa + (OFF_B(s) + kk * 136 + c8 * 4) * 4, src);
        }
        CPA_COMMIT();
    };

    issue(0);
    const int arow = wm * 64;
    const int bcol = wn * 64;

    for (int kt = 0; kt < KT; kt++) {
        CPA_WAIT(0);
        __syncthreads();
        if (kt + 1 < KT) issue(kt + 1);
        const unsigned* As = sm + OFF_A(kt & 1);
        const unsigned* Bs = sm + OFF_B(kt & 1);
        #pragma unroll
        for (int ks = 0; ks < 4; ks++) {
            int c = ks * 8 + tg;
            unsigned a[4][4];
            #pragma unroll
            for (int mi = 0; mi < 4; mi++) {
                int r = arow + mi * 16 + g;
                uint2 t0 = *(const uint2*)(As + r * 40 + ks * 8 + tg * 2);
                uint2 t1 = *(const uint2*)(As + (r + 8) * 40 + ks * 8 + tg * 2);
                a[mi][0] = t0.x; a[mi][1] = t1.x; a[mi][2] = t0.y; a[mi][3] = t1.y;
            }
            unsigned b[8][2];
            #pragma unroll
            for (int ni = 0; ni < 8; ni++) {
                int nn = bcol + ni * 8 + g;
                b[ni][0] = Bs[c * 136 + nn];
                b[ni][1] = Bs[(c + 4) * 136 + nn];
            }
            #pragma unroll
            for (int mi = 0; mi < 4; mi++)
                #pragma unroll
                for (int ni = 0; ni < 8; ni++)
                    MMA_TF32(acc[mi][ni], a[mi], b[ni]);
        }
    }
    __syncthreads();

    // epilogue: acc -> smem [128][132], pair G/U, write g_H permuted + rounded
    float* Hs = (float*)sm;
    #pragma unroll
    for (int mi = 0; mi < 4; mi++) {
        int r1 = arow + mi * 16 + g, r2 = r1 + 8;
        #pragma unroll
        for (int ni = 0; ni < 8; ni++) {
            int cc = bcol + ni * 8 + 2 * tg;
            float* c = acc[mi][ni];
            *(float2*)(Hs + r1 * 132 + cc) = make_float2(c[0], c[1]);
            *(float2*)(Hs + r2 * 132 + cc) = make_float2(c[2], c[3]);
        }
    }
    __syncthreads();
    #pragma unroll
    for (int i = 0; i < 64; i++) {
        int e = tid + i * 128;
        int r = e >> 6, cc = e & 63;
        float gv = Hs[r * 132 + cc];
        float uv = Hs[r * 132 + 64 + cc];
        g_H[(size_t)(m0 + r) * IEXP + n0 + p8(cc)] =
            __uint_as_float(f2tf32(siluf(gv) * uv));
    }
}

// ======================================================================
// GEMM 2: out = cs*(H@Wd) + cx*x + cc0*c0 + cc1*c1
// CTA: 128 threads (4 warps, 2x2), tile M=128 x N=128, warp m64xn64,
// 2-stage cp.async, 3 CTAs/SM. A (g_H) is k-octet-permuted -> LDS.64 frags.
// ======================================================================
__global__ __launch_bounds__(128, 3) void gemm_down(
    const float* __restrict__ X,
    const float* __restrict__ ceC,
    float* __restrict__ out)
{
    extern __shared__ unsigned sm[];
    const uint32_t sa = smem_u32(sm);
    const int tid = threadIdx.x;
    const int lane = tid & 31, wid = tid >> 5;
    const int wm = wid & 1, wn = wid >> 1;
    const int g = lane >> 2, tg = lane & 3;
    const int m0 = blockIdx.x * 128;
    const int n0 = blockIdx.y * 128;
    const int KT = IEXP / 32;

    float acc[4][8][4] = {};

    auto issue = [&](int kt) {
        int s = kt & 1, k0 = kt * 32;
        #pragma unroll
        for (int i = 0; i < 8; i++) {
            int e = tid + i * 128;
            int r = e >> 3, q = e & 7;
            cpa16(sa + (OFF_A(s) + r * 40 + q * 4) * 4,
                  g_H + (size_t)(m0 + r) * IEXP + k0 + q * 4);
        }
        #pragma unroll
        for (int i = 0; i < 8; i++) {
            int e = tid + i * 128;
            int kk = e >> 5, c8 = e & 31;
            cpa16(sa + (OFF_B(s) + kk * 136 + c8 * 4) * 4,
                  g_Wd32 + (size_t)(k0 + kk) * DHID + n0 + c8 * 4);
        }
        CPA_COMMIT();
    };

    issue(0);
    const int arow = wm * 64;
    const int bcol = wn * 64;

    for (int kt = 0; kt < KT; kt++) {
        CPA_WAIT(0);
        __syncthreads();
        if (kt + 1 < KT) issue(kt + 1);
        const unsigned* As = sm + OFF_A(kt & 1);
        const unsigned* Bs = sm + OFF_B(kt & 1);
        #pragma unroll
        for (int ks = 0; ks < 4; ks++) {
            int c = ks * 8 + tg;
            unsigned a[4][4];
            #pragma unroll
            for (int mi = 0; mi < 4; mi++) {
                int r = arow + mi * 16 + g;
                uint2 t0 = *(const uint2*)(As + r * 40 + ks * 8 + tg * 2);
                uint2 t1 = *(const uint2*)(As + (r + 8) * 40 + ks * 8 + tg * 2);
                a[mi][0] = t0.x; a[mi][1] = t1.x; a[mi][2] = t0.y; a[mi][3] = t1.y;
            }
            unsigned b[8][2];
            #pragma unroll
            for (int ni = 0; ni < 8; ni++) {
                int nn = bcol + ni * 8 + g;
                b[ni][0] = Bs[c * 136 + nn];
                b[ni][1] = Bs[(c + 4) * 136 + nn];
            }
            #pragma unroll
            for (int mi = 0; mi < 4; mi++)
                #pragma unroll
                for (int ni = 0; ni < 8; ni++)
                    MMA_TF32(acc[mi][ni], a[mi], b[ni]);
        }
    }

    // epilogue: fold routing coefficients, direct from regs
    const float* c0 = ceC;
    const float* c1 = ceC + DHID;
    #pragma unroll
    for (int mi = 0; mi < 4; mi++) {
        int r1 = m0 + arow + mi * 16 + g;
        int r2 = r1 + 8;
        float cx1 = g_coef[r1 * 4 + 0], cc01 = g_coef[r1 * 4 + 1],
              cc11 = g_coef[r1 * 4 + 2], cs1 = g_coef[r1 * 4 + 3];
        float cx2 = g_coef[r2 * 4 + 0], cc02 = g_coef[r2 * 4 + 1],
              cc12 = g_coef[r2 * 4 + 2], cs2 = g_coef[r2 * 4 + 3];
        #pragma unroll
        for (int ni = 0; ni < 8; ni++) {
            int nn = n0 + bcol + ni * 8 + 2 * tg;
            float* c = acc[mi][ni];
            float2 x1 = *(const float2*)(X + (size_t)r1 * DHID + nn);
            float2 x2 = *(const float2*)(X + (size_t)r2 * DHID + nn);
            float2 v0 = *(const float2*)(c0 + nn);
            float2 v1 = *(const float2*)(c1 + nn);
            float2 o1, o2;
            o1.x = cs1 * c[0] + cx1 * x1.x + cc01 * v0.x + cc11 * v1.x;
            o1.y = cs1 * c[1] + cx1 * x1.y + cc01 * v0.y + cc11 * v1.y;
            o2.x = cs2 * c[2] + cx2 * x2.x + cc02 * v0.x + cc12 * v1.x;
            o2.y = cs2 * c[3] + cx2 * x2.y + cc02 * v0.y + cc12 * v1.y;
            *(float2*)(out + (size_t)r1 * DHID + nn) = o1;
            *(float2*)(out + (size_t)r2 * DHID + nn) = o2;
        }
    }
}

// ======================================================================
extern "C" void kernel_launch(void* const* d_in, const int* in_sizes, int n_in,
                              void* d_out, int out_size)
{
    const float* X    = (const float*)d_in[0];
    const float* W1   = (const float*)d_in[1];
    const float* W2   = (const float*)d_in[2];
    const float* ceWg = (const float*)d_in[3];
    const float* ceC  = (const float*)d_in[4];
    const float* Wg   = (const float*)d_in[5];
    const float* Wu   = (const float*)d_in[6];
    const float* Wd   = (const float*)d_in[7];
    float* out = (float*)d_out;
    float* logits = out + (size_t)NTOK * DHID;

    cudaFuncSetAttribute(gemm_gateup, cudaFuncAttributeMaxDynamicSharedMemorySize, SMEM_BYTES);
    cudaFuncSetAttribute(gemm_down, cudaFuncAttributeMaxDynamicSharedMemorySize, SMEM_BYTES);

    float *pX32, *pWg32, *pWu32, *pWd32;
    cudaGetSymbolAddress((void**)&pX32, g_X32);
    cudaGetSymbolAddress((void**)&pWg32, g_Wg32);
    cudaGetSymbolAddress((void**)&pWu32, g_Wu32);
    cudaGetSymbolAddress((void**)&pWd32, g_Wd32);

    // Launch order: gemm_gateup at index 5 (ncu -s 5 -c 1 captures it).
    round_perm_k<<<1024, 256>>>(X, pX32, NTOK * DHID / 8);      // 0 (X: round+permute)
    round_tf32_k<<<2048, 256>>>(Wg, pWg32, DHID * IEXP / 4);    // 1
    round_tf32_k<<<2048, 256>>>(Wu, pWu32, DHID * IEXP / 4);    // 2
    round_tf32_k<<<2048, 256>>>(Wd, pWd32, IEXP * DHID / 4);    // 3
    router_gemm_tanh<<<NTOK / 64, 256>>>(X, W1);                // 4
    gemm_gateup<<<dim3(NTOK / 128, IEXP / 64), 128, SMEM_BYTES>>>();  // 5 <- profiled
    router_combine<<<NTOK, 128>>>(X, W2, ceWg, logits);         // 6
    gemm_down<<<dim3(NTOK / 128, DHID / 128), 128, SMEM_BYTES>>>(X, ceC, out);  // 7
}